// round 11
// baseline (speedup 1.0000x reference)
#include <cuda_runtime.h>
#include <cuda_bf16.h>
#include <math.h>

// Problem dims
#define B_ 32
#define T_ 64
#define P_ 10
#define I_ 1024
#define H_ 1024
#define C_ 8
#define G4 4096
#define M_ (B_*T_*P_)     // 20480
#define N5 5120           // Wh(1024) + Whh(4096) rows merged

// Scratch (device globals; no allocation allowed)
__device__ float d_xwx[(size_t)T_*B_*P_*H_];   // 80 MB: x@Wx^T, layout [t][b][p][h]
__device__ float d_p5[4*B_*N5];                // split-K(4) partials of h@[Wh|Whh]^T
__device__ float d_emb[B_*H_];                 // attention-pooled features
__device__ float d_h[B_*H_];                   // LSTM hidden
__device__ float d_c[B_*H_];                   // LSTM cell

__device__ __forceinline__ float tanh_fast(float x) {
    float y; asm("tanh.approx.f32 %0, %1;" : "=f"(y) : "f"(x)); return y;
}
__device__ __forceinline__ float sigmoidf(float x) {
    return 1.0f / (1.0f + expf(-x));
}

// ---------------------------------------------------------------------------
// zero initial state
// ---------------------------------------------------------------------------
__global__ void zero_state() {
    int i0 = blockIdx.x * 256 + threadIdx.x;
    for (int i = i0; i < B_*H_; i += 128*256) { d_h[i] = 0.0f; d_c[i] = 0.0f; }
}

// ---------------------------------------------------------------------------
// sgemm_xwx: xwx[t,b,p,h] = sum_i x[b,t,p,i]*Wx[h,i]   (R10 proven)
// ---------------------------------------------------------------------------
__global__ __launch_bounds__(256, 2) void sgemm_xwx(
    const float* __restrict__ A, const float* __restrict__ Bm)
{
    __shared__ float As[8][128];
    __shared__ float Bs[8][128];
    const int tid = threadIdx.x;
    const int m0 = blockIdx.y * 128;
    const int n0 = blockIdx.x * 128;
    const int tx = tid & 15;
    const int ty = tid >> 4;

    float acc[8][8];
#pragma unroll
    for (int i = 0; i < 8; i++)
#pragma unroll
        for (int j = 0; j < 8; j++) acc[i][j] = 0.0f;

    const int ar = tid >> 1;
    const int ac = (tid & 1) * 4;
    const float* Aptr = A  + (size_t)(m0 + ar) * I_ + ac;
    const float* Bptr = Bm + (size_t)(n0 + ar) * I_ + ac;

    float4 av = *(const float4*)(Aptr);
    float4 bv = *(const float4*)(Bptr);

    for (int kb = 0; kb < I_; kb += 8) {
        As[ac+0][ar] = av.x; As[ac+1][ar] = av.y; As[ac+2][ar] = av.z; As[ac+3][ar] = av.w;
        Bs[ac+0][ar] = bv.x; Bs[ac+1][ar] = bv.y; Bs[ac+2][ar] = bv.z; Bs[ac+3][ar] = bv.w;
        __syncthreads();

        float4 av_n = av, bv_n = bv;
        if (kb + 8 < I_) {
            av_n = *(const float4*)(Aptr + kb + 8);
            bv_n = *(const float4*)(Bptr + kb + 8);
        }
#pragma unroll
        for (int kk = 0; kk < 8; kk++) {
            float a_f[8], b_f[8];
            *(float4*)(a_f)     = *(const float4*)&As[kk][ty*8];
            *(float4*)(a_f + 4) = *(const float4*)&As[kk][ty*8 + 4];
            *(float4*)(b_f)     = *(const float4*)&Bs[kk][tx*4];
            *(float4*)(b_f + 4) = *(const float4*)&Bs[kk][64 + tx*4];
#pragma unroll
            for (int i = 0; i < 8; i++)
#pragma unroll
                for (int j = 0; j < 8; j++)
                    acc[i][j] += a_f[i] * b_f[j];
        }
        __syncthreads();
        av = av_n; bv = bv_n;
    }

#pragma unroll
    for (int i = 0; i < 8; i++) {
        int r   = m0 + ty*8 + i;
        int b   = r / (T_*P_);
        int rem = r % (T_*P_);
        int t   = rem / P_;
        int p   = rem % P_;
        float* o = d_xwx + (size_t)((t*B_ + b)*P_ + p) * H_ + n0;
        *(float4*)(o + tx*4)      = *(float4*)&acc[i][0];
        *(float4*)(o + 64 + tx*4) = *(float4*)&acc[i][4];
    }
}

// ---------------------------------------------------------------------------
// kh: h @ [Wh | Whh]^T, N=5120, split-K(4).  grid (80,4), 256t.  (R5 proven)
// ---------------------------------------------------------------------------
__global__ __launch_bounds__(256) void kh(const float* __restrict__ Wh,
                                          const float* __restrict__ Whh)
{
    __shared__ float u_s[64][32];   // [k][b]
    __shared__ float w_s[64][64];   // [k][n_local]
    const int tid = threadIdx.x;
    const int n0 = blockIdx.x * 64;
    const int k_start = blockIdx.y * 256;
    const int tn = tid & 15;
    const int tb = tid >> 4;

    float acc[2][4] = {{0,0,0,0},{0,0,0,0}};

    for (int cb = 0; cb < 256; cb += 64) {
        const int kb = k_start + cb;
#pragma unroll
        for (int l = tid*4; l < 2048; l += 1024) {
            int b  = l >> 6;
            int i0 = l & 63;
            float4 uv = *(const float4*)&d_h[b * H_ + kb + i0];
            u_s[i0+0][b] = uv.x; u_s[i0+1][b] = uv.y;
            u_s[i0+2][b] = uv.z; u_s[i0+3][b] = uv.w;
        }
#pragma unroll
        for (int l = tid; l < 1024; l += 256) {
            int r = l >> 4;
            int q = (l & 15) * 4;
            int n = n0 + r;
            const float* Wrow = (n < 1024) ? (Wh + (size_t)n * 1024)
                                           : (Whh + (size_t)(n - 1024) * 1024);
            float4 wv = *(const float4*)&Wrow[kb + q];
            w_s[q+0][r] = wv.x; w_s[q+1][r] = wv.y;
            w_s[q+2][r] = wv.z; w_s[q+3][r] = wv.w;
        }
        __syncthreads();
#pragma unroll
        for (int i = 0; i < 64; i++) {
            float2 uu = *(const float2*)&u_s[i][tb*2];
            float4 ww = *(const float4*)&w_s[i][tn*4];
            acc[0][0] += uu.x*ww.x; acc[0][1] += uu.x*ww.y;
            acc[0][2] += uu.x*ww.z; acc[0][3] += uu.x*ww.w;
            acc[1][0] += uu.y*ww.x; acc[1][1] += uu.y*ww.y;
            acc[1][2] += uu.y*ww.z; acc[1][3] += uu.y*ww.w;
        }
        __syncthreads();
    }

    const int ks = blockIdx.y;
#pragma unroll
    for (int bb = 0; bb < 2; bb++) {
        int b = tb*2 + bb;
#pragma unroll
        for (int nn = 0; nn < 4; nn++)
            d_p5[(ks*B_ + b)*N5 + n0 + tn*4 + nn] = acc[bb][nn];
    }
}

// ---------------------------------------------------------------------------
// katt: fused scores + softmax + attention pooling.  grid 32 (b), 1024 threads.
//   phase 1: thread h: a[h] = b_att[h] + sum4 p5;  sp[p] += v[h]*tanh(xw+a)
//   reduce: warp shfl -> wsum[10][33] -> tid<10 total -> softmax -> al_s[10]
//   phase 2: thread i: d_emb[b][i] = sum_p al[p]*x[b,t,p,i]
// ---------------------------------------------------------------------------
__global__ __launch_bounds__(1024) void katt(
    int t, const float* __restrict__ b_att, const float* __restrict__ v,
    const float* __restrict__ x)
{
    __shared__ float wsum[P_][33];
    __shared__ float sc_s[P_];
    __shared__ float al_s[P_];

    const int b   = blockIdx.x;
    const int tid = threadIdx.x;
    const int h   = tid;

    // phase 1: per-h score contributions
    float a = __ldg(&b_att[h]);
#pragma unroll
    for (int ks = 0; ks < 4; ks++) a += d_p5[(ks*B_ + b)*N5 + h];
    const float vh = __ldg(&v[h]);
    const float* xw = &d_xwx[(size_t)((t*B_ + b)*P_) * H_ + h];

    float sp[P_];
#pragma unroll
    for (int p = 0; p < P_; p++)
        sp[p] = vh * tanh_fast(xw[p*H_] + a);

    // warp reduce all 10
#pragma unroll
    for (int p = 0; p < P_; p++) {
#pragma unroll
        for (int o = 16; o; o >>= 1) sp[p] += __shfl_xor_sync(0xffffffffu, sp[p], o);
    }
    const int warp = tid >> 5, lane = tid & 31;
    if (lane == 0) {
#pragma unroll
        for (int p = 0; p < P_; p++) wsum[p][warp] = sp[p];
    }
    __syncthreads();
    if (tid < P_) {
        float s = 0.0f;
#pragma unroll
        for (int w = 0; w < 32; w++) s += wsum[tid][w];
        sc_s[tid] = s;
    }
    __syncthreads();
    if (tid < P_) {
        float mx = sc_s[0];
#pragma unroll
        for (int p = 1; p < P_; p++) mx = fmaxf(mx, sc_s[p]);
        al_s[tid] = expf(sc_s[tid] - mx);
    }
    __syncthreads();

    // phase 2: pooling (each thread also normalizes locally — broadcast reads)
    float al[P_], ssum = 0.0f;
#pragma unroll
    for (int p = 0; p < P_; p++) { al[p] = al_s[p]; ssum += al[p]; }
    float inv = 1.0f / ssum;

    const float* xb = &x[(size_t)((b*T_ + t)*P_) * I_ + tid];
    float e = 0.0f;
#pragma unroll
    for (int p = 0; p < P_; p++) e += al[p] * __ldg(&xb[p*I_]);
    d_emb[b*H_ + tid] = e * inv;
}

// ---------------------------------------------------------------------------
// kgc: emb @ Wih^T (gate-grouped rows, full K) + fused LSTM cell update.
// grid 64 (j-chunk 16), 256 threads.  Block rows r=0..63: gate g=r>>4,
// j = j0 + (r&15).  Epilogue: acc -> smem, then 512 (j,b) cell updates
// using 4 gates + 4 kh gate partials + biases.
// ---------------------------------------------------------------------------
__global__ __launch_bounds__(256) void kgc(
    const float* __restrict__ Wih,
    const float* __restrict__ bih, const float* __restrict__ bhh)
{
    __shared__ float u_s[64][32];
    __shared__ float w_s[64][64];
    __shared__ float red[64][33];

    const int tid = threadIdx.x;
    const int j0  = blockIdx.x * 16;
    const int tn = tid & 15;
    const int tb = tid >> 4;

    float acc[2][4] = {{0,0,0,0},{0,0,0,0}};

    for (int kb = 0; kb < 1024; kb += 64) {
#pragma unroll
        for (int l = tid*4; l < 2048; l += 1024) {
            int b  = l >> 6;
            int i0 = l & 63;
            float4 uv = *(const float4*)&d_emb[b * H_ + kb + i0];
            u_s[i0+0][b] = uv.x; u_s[i0+1][b] = uv.y;
            u_s[i0+2][b] = uv.z; u_s[i0+3][b] = uv.w;
        }
#pragma unroll
        for (int l = tid; l < 1024; l += 256) {
            int r = l >> 4;
            int q = (l & 15) * 4;
            int gr = (r >> 4) * 1024 + j0 + (r & 15);
            float4 wv = *(const float4*)&Wih[(size_t)gr * 1024 + kb + q];
            w_s[q+0][r] = wv.x; w_s[q+1][r] = wv.y;
            w_s[q+2][r] = wv.z; w_s[q+3][r] = wv.w;
        }
        __syncthreads();
#pragma unroll
        for (int i = 0; i < 64; i++) {
            float2 uu = *(const float2*)&u_s[i][tb*2];
            float4 ww = *(const float4*)&w_s[i][tn*4];
            acc[0][0] += uu.x*ww.x; acc[0][1] += uu.x*ww.y;
            acc[0][2] += uu.x*ww.z; acc[0][3] += uu.x*ww.w;
            acc[1][0] += uu.y*ww.x; acc[1][1] += uu.y*ww.y;
            acc[1][2] += uu.y*ww.z; acc[1][3] += uu.y*ww.w;
        }
        __syncthreads();
    }

    // stash accumulators: red[r][b]
#pragma unroll
    for (int nn = 0; nn < 4; nn++)
#pragma unroll
        for (int bb = 0; bb < 2; bb++)
            red[tn*4 + nn][tb*2 + bb] = acc[bb][nn];
    __syncthreads();

    // fused cell: 512 (j,b) items over 256 threads
#pragma unroll
    for (int it = 0; it < 2; it++) {
        int l  = tid + it*256;
        int b  = l & 31;
        int jl = l >> 5;             // 0..15
        int j  = j0 + jl;
        float g4[4];
#pragma unroll
        for (int g = 0; g < 4; g++) {
            int m = g*1024 + j;
            float s = red[g*16 + jl][b] + __ldg(&bih[m]) + __ldg(&bhh[m]);
#pragma unroll
            for (int ks = 0; ks < 4; ks++)
                s += d_p5[(ks*B_ + b)*N5 + 1024 + m];
            g4[g] = s;
        }
        float ig = sigmoidf(g4[0]);
        float fg = sigmoidf(g4[1]);
        float gg = tanhf(g4[2]);
        float og = sigmoidf(g4[3]);
        int idx = b*H_ + j;
        float cn = fg * d_c[idx] + ig * gg;
        d_c[idx] = cn;
        d_h[idx] = og * tanhf(cn);
    }
}

// ---------------------------------------------------------------------------
// Final FC
// ---------------------------------------------------------------------------
__global__ __launch_bounds__(256) void kfc(const float* __restrict__ Wfc,
                                           const float* __restrict__ bfc,
                                           float* __restrict__ out)
{
    int b = blockIdx.x;
    int w = threadIdx.x >> 5;
    int lane = threadIdx.x & 31;
    const float* h = &d_h[b*H_];
    float acc = 0.0f;
    for (int i = lane; i < H_; i += 32) acc += h[i] * Wfc[w*H_ + i];
#pragma unroll
    for (int o = 16; o; o >>= 1) acc += __shfl_xor_sync(0xffffffffu, acc, o);
    if (lane == 0) out[b*C_ + w] = acc + bfc[w];
}

// ---------------------------------------------------------------------------
extern "C" void kernel_launch(void* const* d_in, const int* in_sizes, int n_in,
                              void* d_out, int out_size)
{
    const float* x    = (const float*)d_in[0];
    const float* Wx   = (const float*)d_in[1];
    const float* Wh   = (const float*)d_in[2];
    const float* batt = (const float*)d_in[3];
    const float* v    = (const float*)d_in[4];
    const float* Wih  = (const float*)d_in[5];
    const float* Whh  = (const float*)d_in[6];
    const float* bih  = (const float*)d_in[7];
    const float* bhh  = (const float*)d_in[8];
    const float* Wfc  = (const float*)d_in[9];
    const float* bfc  = (const float*)d_in[10];
    float* out = (float*)d_out;

    zero_state<<<128, 256>>>();
    sgemm_xwx<<<dim3(H_/128, M_/128), 256>>>(x, Wx);

    for (int t = 0; t < T_; t++) {
        kh<<<dim3(80, 4), 256>>>(Wh, Whh);
        katt<<<B_, 1024>>>(t, batt, v, x);
        kgc<<<64, 256>>>(Wih, bih, bhh);
    }
    kfc<<<32, 256>>>(Wfc, bfc, out);
}

// round 12
// speedup vs baseline: 1.3316x; 1.3316x over previous
#include <cuda_runtime.h>
#include <cuda_bf16.h>
#include <math.h>

// Problem dims
#define B_ 32
#define T_ 64
#define P_ 10
#define I_ 1024
#define H_ 1024
#define C_ 8
#define G4 4096
#define M_ (B_*T_*P_)     // 20480
#define N5 5120           // Wh(1024) + Whh(4096) rows merged

// Scratch (device globals; no allocation allowed)
__device__ float d_xwx[(size_t)T_*B_*P_*H_];   // 80 MB: x@Wx^T, layout [t][b][p][h]
__device__ float d_p5[4*B_*N5];                // split-K(4) partials of h@[Wh|Whh]^T
__device__ float d_gpart[2*B_*G4];             // split-K(2) partials of emb@Wih^T
__device__ float d_emb[B_*H_];                 // attention-pooled features
__device__ float d_h[B_*H_];                   // LSTM hidden
__device__ float d_c[B_*H_];                   // LSTM cell

__device__ __forceinline__ float tanh_fast(float x) {
    float y; asm("tanh.approx.f32 %0, %1;" : "=f"(y) : "f"(x)); return y;
}
__device__ __forceinline__ float sigmoidf(float x) {
    return 1.0f / (1.0f + expf(-x));
}

// ---------------------------------------------------------------------------
// zero initial state
// ---------------------------------------------------------------------------
__global__ void zero_state() {
    int i0 = blockIdx.x * 256 + threadIdx.x;
    for (int i = i0; i < B_*H_; i += 128*256) { d_h[i] = 0.0f; d_c[i] = 0.0f; }
}

// ---------------------------------------------------------------------------
// sgemm_xwx: xwx[t,b,p,h] = sum_i x[b,t,p,i]*Wx[h,i]   (R10 proven)
// ---------------------------------------------------------------------------
__global__ __launch_bounds__(256, 2) void sgemm_xwx(
    const float* __restrict__ A, const float* __restrict__ Bm)
{
    __shared__ float As[8][128];
    __shared__ float Bs[8][128];
    const int tid = threadIdx.x;
    const int m0 = blockIdx.y * 128;
    const int n0 = blockIdx.x * 128;
    const int tx = tid & 15;
    const int ty = tid >> 4;

    float acc[8][8];
#pragma unroll
    for (int i = 0; i < 8; i++)
#pragma unroll
        for (int j = 0; j < 8; j++) acc[i][j] = 0.0f;

    const int ar = tid >> 1;
    const int ac = (tid & 1) * 4;
    const float* Aptr = A  + (size_t)(m0 + ar) * I_ + ac;
    const float* Bptr = Bm + (size_t)(n0 + ar) * I_ + ac;

    float4 av = *(const float4*)(Aptr);
    float4 bv = *(const float4*)(Bptr);

    for (int kb = 0; kb < I_; kb += 8) {
        As[ac+0][ar] = av.x; As[ac+1][ar] = av.y; As[ac+2][ar] = av.z; As[ac+3][ar] = av.w;
        Bs[ac+0][ar] = bv.x; Bs[ac+1][ar] = bv.y; Bs[ac+2][ar] = bv.z; Bs[ac+3][ar] = bv.w;
        __syncthreads();

        float4 av_n = av, bv_n = bv;
        if (kb + 8 < I_) {
            av_n = *(const float4*)(Aptr + kb + 8);
            bv_n = *(const float4*)(Bptr + kb + 8);
        }
#pragma unroll
        for (int kk = 0; kk < 8; kk++) {
            float a_f[8], b_f[8];
            *(float4*)(a_f)     = *(const float4*)&As[kk][ty*8];
            *(float4*)(a_f + 4) = *(const float4*)&As[kk][ty*8 + 4];
            *(float4*)(b_f)     = *(const float4*)&Bs[kk][tx*4];
            *(float4*)(b_f + 4) = *(const float4*)&Bs[kk][64 + tx*4];
#pragma unroll
            for (int i = 0; i < 8; i++)
#pragma unroll
                for (int j = 0; j < 8; j++)
                    acc[i][j] += a_f[i] * b_f[j];
        }
        __syncthreads();
        av = av_n; bv = bv_n;
    }

#pragma unroll
    for (int i = 0; i < 8; i++) {
        int r   = m0 + ty*8 + i;
        int b   = r / (T_*P_);
        int rem = r % (T_*P_);
        int t   = rem / P_;
        int p   = rem % P_;
        float* o = d_xwx + (size_t)((t*B_ + b)*P_ + p) * H_ + n0;
        *(float4*)(o + tx*4)      = *(float4*)&acc[i][0];
        *(float4*)(o + 64 + tx*4) = *(float4*)&acc[i][4];
    }
}

// ---------------------------------------------------------------------------
// kh: h @ [Wh | Whh]^T, N=5120, split-K(4).  grid (80,4), 256t.  (R5 proven)
// ---------------------------------------------------------------------------
__global__ __launch_bounds__(256) void kh(const float* __restrict__ Wh,
                                          const float* __restrict__ Whh)
{
    __shared__ float u_s[64][32];   // [k][b]
    __shared__ float w_s[64][64];   // [k][n_local]
    const int tid = threadIdx.x;
    const int n0 = blockIdx.x * 64;
    const int k_start = blockIdx.y * 256;
    const int tn = tid & 15;
    const int tb = tid >> 4;

    float acc[2][4] = {{0,0,0,0},{0,0,0,0}};

    for (int cb = 0; cb < 256; cb += 64) {
        const int kb = k_start + cb;
#pragma unroll
        for (int l = tid*4; l < 2048; l += 1024) {
            int b  = l >> 6;
            int i0 = l & 63;
            float4 uv = *(const float4*)&d_h[b * H_ + kb + i0];
            u_s[i0+0][b] = uv.x; u_s[i0+1][b] = uv.y;
            u_s[i0+2][b] = uv.z; u_s[i0+3][b] = uv.w;
        }
#pragma unroll
        for (int l = tid; l < 1024; l += 256) {
            int r = l >> 4;
            int q = (l & 15) * 4;
            int n = n0 + r;
            const float* Wrow = (n < 1024) ? (Wh + (size_t)n * 1024)
                                           : (Whh + (size_t)(n - 1024) * 1024);
            float4 wv = *(const float4*)&Wrow[kb + q];
            w_s[q+0][r] = wv.x; w_s[q+1][r] = wv.y;
            w_s[q+2][r] = wv.z; w_s[q+3][r] = wv.w;
        }
        __syncthreads();
#pragma unroll
        for (int i = 0; i < 64; i++) {
            float2 uu = *(const float2*)&u_s[i][tb*2];
            float4 ww = *(const float4*)&w_s[i][tn*4];
            acc[0][0] += uu.x*ww.x; acc[0][1] += uu.x*ww.y;
            acc[0][2] += uu.x*ww.z; acc[0][3] += uu.x*ww.w;
            acc[1][0] += uu.y*ww.x; acc[1][1] += uu.y*ww.y;
            acc[1][2] += uu.y*ww.z; acc[1][3] += uu.y*ww.w;
        }
        __syncthreads();
    }

    const int ks = blockIdx.y;
#pragma unroll
    for (int bb = 0; bb < 2; bb++) {
        int b = tb*2 + bb;
#pragma unroll
        for (int nn = 0; nn < 4; nn++)
            d_p5[(ks*B_ + b)*N5 + n0 + tn*4 + nn] = acc[bb][nn];
    }
}

// ---------------------------------------------------------------------------
// katt: fused scores + softmax + attention pooling.  grid 32 (b), 1024t.
// (measured 7.2us in R11; replaces kscore + kpool + one gap)
// ---------------------------------------------------------------------------
__global__ __launch_bounds__(1024) void katt(
    int t, const float* __restrict__ b_att, const float* __restrict__ v,
    const float* __restrict__ x)
{
    __shared__ float wsum[P_][33];
    __shared__ float sc_s[P_];
    __shared__ float al_s[P_];

    const int b   = blockIdx.x;
    const int tid = threadIdx.x;
    const int h   = tid;

    // phase 1: per-h score contributions
    float a = __ldg(&b_att[h]);
#pragma unroll
    for (int ks = 0; ks < 4; ks++) a += d_p5[(ks*B_ + b)*N5 + h];
    const float vh = __ldg(&v[h]);
    const float* xw = &d_xwx[(size_t)((t*B_ + b)*P_) * H_ + h];

    float sp[P_];
#pragma unroll
    for (int p = 0; p < P_; p++)
        sp[p] = vh * tanh_fast(xw[p*H_] + a);

#pragma unroll
    for (int p = 0; p < P_; p++) {
#pragma unroll
        for (int o = 16; o; o >>= 1) sp[p] += __shfl_xor_sync(0xffffffffu, sp[p], o);
    }
    const int warp = tid >> 5, lane = tid & 31;
    if (lane == 0) {
#pragma unroll
        for (int p = 0; p < P_; p++) wsum[p][warp] = sp[p];
    }
    __syncthreads();
    if (tid < P_) {
        float s = 0.0f;
#pragma unroll
        for (int w = 0; w < 32; w++) s += wsum[tid][w];
        sc_s[tid] = s;
    }
    __syncthreads();
    if (tid < P_) {
        float mx = sc_s[0];
#pragma unroll
        for (int p = 1; p < P_; p++) mx = fmaxf(mx, sc_s[p]);
        al_s[tid] = expf(sc_s[tid] - mx);
    }
    __syncthreads();

    // phase 2: pooling
    float al[P_], ssum = 0.0f;
#pragma unroll
    for (int p = 0; p < P_; p++) { al[p] = al_s[p]; ssum += al[p]; }
    float inv = 1.0f / ssum;

    const float* xb = &x[(size_t)((b*T_ + t)*P_) * I_ + tid];
    float e = 0.0f;
#pragma unroll
    for (int p = 0; p < P_; p++) e += al[p] * __ldg(&xb[p*I_]);
    d_emb[b*H_ + tid] = e * inv;
}

// ---------------------------------------------------------------------------
// kge: emb @ Wih^T, split-K(2).  grid (64, 2), 256 threads.  (R10 proven)
// ---------------------------------------------------------------------------
__global__ __launch_bounds__(256) void kge(const float* __restrict__ Wih)
{
    __shared__ float u_s[64][32];
    __shared__ float w_s[64][64];
    const int tid = threadIdx.x;
    const int n0 = blockIdx.x * 64;
    const int k_start = blockIdx.y * 512;
    const int tn = tid & 15;
    const int tb = tid >> 4;

    float acc[2][4] = {{0,0,0,0},{0,0,0,0}};

    for (int cb = 0; cb < 512; cb += 64) {
        const int kb = k_start + cb;
#pragma unroll
        for (int l = tid*4; l < 2048; l += 1024) {
            int b  = l >> 6;
            int i0 = l & 63;
            float4 uv = *(const float4*)&d_emb[b * H_ + kb + i0];
            u_s[i0+0][b] = uv.x; u_s[i0+1][b] = uv.y;
            u_s[i0+2][b] = uv.z; u_s[i0+3][b] = uv.w;
        }
#pragma unroll
        for (int l = tid; l < 1024; l += 256) {
            int r = l >> 4;
            int q = (l & 15) * 4;
            float4 wv = *(const float4*)&Wih[(size_t)(n0 + r) * 1024 + kb + q];
            w_s[q+0][r] = wv.x; w_s[q+1][r] = wv.y;
            w_s[q+2][r] = wv.z; w_s[q+3][r] = wv.w;
        }
        __syncthreads();
#pragma unroll
        for (int i = 0; i < 64; i++) {
            float2 uu = *(const float2*)&u_s[i][tb*2];
            float4 ww = *(const float4*)&w_s[i][tn*4];
            acc[0][0] += uu.x*ww.x; acc[0][1] += uu.x*ww.y;
            acc[0][2] += uu.x*ww.z; acc[0][3] += uu.x*ww.w;
            acc[1][0] += uu.y*ww.x; acc[1][1] += uu.y*ww.y;
            acc[1][2] += uu.y*ww.z; acc[1][3] += uu.y*ww.w;
        }
        __syncthreads();
    }

    const int ks = blockIdx.y;
#pragma unroll
    for (int bb = 0; bb < 2; bb++) {
        int b = tb*2 + bb;
#pragma unroll
        for (int nn = 0; nn < 4; nn++)
            d_gpart[(size_t)(ks*B_ + b)*G4 + n0 + tn*4 + nn] = acc[bb][nn];
    }
}

// ---------------------------------------------------------------------------
// kcell: gates = gpart(2) + p5 gate slices(4) + biases -> cell + hidden
// ---------------------------------------------------------------------------
__global__ __launch_bounds__(256) void kcell(const float* __restrict__ bih,
                                             const float* __restrict__ bhh)
{
    int idx = blockIdx.x * 256 + threadIdx.x;   // 32768
    int b = idx >> 10, j = idx & 1023;
    float g4[4];
#pragma unroll
    for (int g = 0; g < 4; g++) {
        int m = g*H_ + j;
        float s = bih[m] + bhh[m];
#pragma unroll
        for (int ks = 0; ks < 2; ks++) s += d_gpart[(size_t)(ks*B_ + b)*G4 + m];
#pragma unroll
        for (int ks = 0; ks < 4; ks++) s += d_p5[(ks*B_ + b)*N5 + 1024 + m];
        g4[g] = s;
    }
    float ig = sigmoidf(g4[0]);
    float fg = sigmoidf(g4[1]);
    float gg = tanhf(g4[2]);
    float og = sigmoidf(g4[3]);
    float cn = fg * d_c[idx] + ig * gg;
    d_c[idx] = cn;
    d_h[idx] = og * tanhf(cn);
}

// ---------------------------------------------------------------------------
// Final FC
// ---------------------------------------------------------------------------
__global__ __launch_bounds__(256) void kfc(const float* __restrict__ Wfc,
                                           const float* __restrict__ bfc,
                                           float* __restrict__ out)
{
    int b = blockIdx.x;
    int w = threadIdx.x >> 5;
    int lane = threadIdx.x & 31;
    const float* h = &d_h[b*H_];
    float acc = 0.0f;
    for (int i = lane; i < H_; i += 32) acc += h[i] * Wfc[w*H_ + i];
#pragma unroll
    for (int o = 16; o; o >>= 1) acc += __shfl_xor_sync(0xffffffffu, acc, o);
    if (lane == 0) out[b*C_ + w] = acc + bfc[w];
}

// ---------------------------------------------------------------------------
extern "C" void kernel_launch(void* const* d_in, const int* in_sizes, int n_in,
                              void* d_out, int out_size)
{
    const float* x    = (const float*)d_in[0];
    const float* Wx   = (const float*)d_in[1];
    const float* Wh   = (const float*)d_in[2];
    const float* batt = (const float*)d_in[3];
    const float* v    = (const float*)d_in[4];
    const float* Wih  = (const float*)d_in[5];
    const float* Whh  = (const float*)d_in[6];
    const float* bih  = (const float*)d_in[7];
    const float* bhh  = (const float*)d_in[8];
    const float* Wfc  = (const float*)d_in[9];
    const float* bfc  = (const float*)d_in[10];
    float* out = (float*)d_out;

    zero_state<<<128, 256>>>();
    sgemm_xwx<<<dim3(H_/128, M_/128), 256>>>(x, Wx);

    for (int t = 0; t < T_; t++) {
        kh<<<dim3(80, 4), 256>>>(Wh, Whh);
        katt<<<B_, 1024>>>(t, batt, v, x);
        kge<<<dim3(64, 2), 256>>>(Wih);
        kcell<<<128, 256>>>(bih, bhh);
    }
    kfc<<<32, 256>>>(Wfc, bfc, out);
}